// round 13
// baseline (speedup 1.0000x reference)
#include <cuda_runtime.h>
#include <cstdint>

// Problem constants (match reference_code)
#define VOC_SIZE 1000000
#define EMBED_DIM 64
#define N_UPD 262144
#define N_Q (4096 * 200)  // 819200 query rows

// Scratch (allocation-free __device__ globals).
// Per-row linked list of updates:
//   g_head[row] = 1 + index of the last update hitting `row` (0 = untouched)
//   g_next[i]   = 1 + index of the previous update hitting the same row
// Invariant: g_head is all-zero at entry to every kernel_launch invocation
// (zero-initialized at module load; a graph memset node restores it at the
// end of each invocation).
__device__ int g_head[1 << 20];   // 4 MB (padded to power of two)
__device__ int g_next[N_UPD];     // 1 MB

typedef unsigned long long u64;

// 32-byte table load with L2 evict_last (sm_103a: modifier requires
// .v8.b32 / .v4.b64 width). Duplicate queries re-read table rows; bias them
// to stay resident in L2.
__device__ __forceinline__ void ldg_evict_last_32B(const float* p,
                                                   u64& x, u64& y, u64& z, u64& w) {
    asm("ld.global.nc.L2::evict_last.v4.b64 {%0,%1,%2,%3}, [%4];"
        : "=l"(x), "=l"(y), "=l"(z), "=l"(w) : "l"(p));
}

// Streaming store (evict-first): output is written once and never re-read.
__device__ __forceinline__ void stg_cs_32B(float* p, u64 x, u64 y, u64 z, u64 w) {
    asm volatile("st.global.cs.v4.b64 [%0], {%1,%2,%3,%4};"
                 :: "l"(p), "l"(x), "l"(y), "l"(z), "l"(w) : "memory");
}

__device__ __forceinline__ u64 pack2(float lo, float hi) {
    return ((u64)__float_as_uint(hi) << 32) | (u64)__float_as_uint(lo);
}
__device__ __forceinline__ float f_lo(u64 v) { return __uint_as_float((unsigned)v); }
__device__ __forceinline__ float f_hi(u64 v) { return __uint_as_float((unsigned)(v >> 32)); }

// K1: build per-row linked lists of updates. Requires g_head == 0 on entry.
// Latency-pinned at ~6.5us regardless of occupancy/ILP config (measured both
// ways); leave as the simple 1-update-per-thread form.
__global__ void link_kernel(const int* __restrict__ indices) {
    int i = blockIdx.x * blockDim.x + threadIdx.x;   // 0 .. N_UPD-1
    int r = indices[i];
    int o = atomicExch(&g_head[r], i + 1);
    g_next[i] = o;
}

// K2: gather. out[q] = table[q] + sum over the update chain of row q.
// 8 threads per 256B row, 32B per thread; each thread handles TWO query rows
// (i, i+N_Q/2). The two chain walks are FUSED into one loop so both rows'
// upd/next loads are in flight together (overlapped long-scoreboard latency)
// instead of walking row 0's chain to completion before starting row 1's.
// Table reads: L2 evict_last. Output: streaming stores.
__global__ void gather_kernel(const float* __restrict__ table,
                              const int* __restrict__ qs,
                              const float* __restrict__ upd,
                              float* __restrict__ out) {
    int t = blockIdx.x * blockDim.x + threadIdx.x;   // 0 .. N_Q*4-1
    int i0 = t >> 3;
    int j  = t & 7;
    int i1 = i0 + (N_Q / 2);

    int r0 = qs[i0];
    int r1 = qs[i1];
    size_t o0 = (size_t)r0 * EMBED_DIM + j * 8;
    size_t o1 = (size_t)r1 * EMBED_DIM + j * 8;

    u64 x0, y0, z0, w0, x1, y1, z1, w1;
    ldg_evict_last_32B(&table[o0], x0, y0, z0, w0);
    ldg_evict_last_32B(&table[o1], x1, y1, z1, w1);
    int p0 = g_head[r0];
    int p1 = g_head[r1];

    if (p0 | p1) {
        float4 sa0 = make_float4(0.f, 0.f, 0.f, 0.f);
        float4 sb0 = make_float4(0.f, 0.f, 0.f, 0.f);
        float4 sa1 = make_float4(0.f, 0.f, 0.f, 0.f);
        float4 sb1 = make_float4(0.f, 0.f, 0.f, 0.f);
        while (p0 | p1) {
            if (p0) {
                int i = p0 - 1;
                const float4* up = reinterpret_cast<const float4*>(
                    &upd[(size_t)i * EMBED_DIM + j * 8]);
                float4 da = __ldg(up);
                float4 db = __ldg(up + 1);
                sa0.x += da.x; sa0.y += da.y; sa0.z += da.z; sa0.w += da.w;
                sb0.x += db.x; sb0.y += db.y; sb0.z += db.z; sb0.w += db.w;
                p0 = g_next[i];
            }
            if (p1) {
                int i = p1 - 1;
                const float4* up = reinterpret_cast<const float4*>(
                    &upd[(size_t)i * EMBED_DIM + j * 8]);
                float4 da = __ldg(up);
                float4 db = __ldg(up + 1);
                sa1.x += da.x; sa1.y += da.y; sa1.z += da.z; sa1.w += da.w;
                sb1.x += db.x; sb1.y += db.y; sb1.z += db.z; sb1.w += db.w;
                p1 = g_next[i];
            }
        }
        x0 = pack2(f_lo(x0) + sa0.x, f_hi(x0) + sa0.y);
        y0 = pack2(f_lo(y0) + sa0.z, f_hi(y0) + sa0.w);
        z0 = pack2(f_lo(z0) + sb0.x, f_hi(z0) + sb0.y);
        w0 = pack2(f_lo(w0) + sb0.z, f_hi(w0) + sb0.w);
        x1 = pack2(f_lo(x1) + sa1.x, f_hi(x1) + sa1.y);
        y1 = pack2(f_lo(y1) + sa1.z, f_hi(y1) + sa1.w);
        z1 = pack2(f_lo(z1) + sb1.x, f_hi(z1) + sb1.y);
        w1 = pack2(f_lo(w1) + sb1.z, f_hi(w1) + sb1.w);
    }

    stg_cs_32B(&out[(size_t)i0 * EMBED_DIM + j * 8], x0, y0, z0, w0);
    stg_cs_32B(&out[(size_t)i1 * EMBED_DIM + j * 8], x1, y1, z1, w1);
}

extern "C" void kernel_launch(void* const* d_in, const int* in_sizes, int n_in,
                              void* d_out, int out_size) {
    // metadata order: kernel (f32), indices (i32), emb_update (f32), qs (i32)
    const float* table   = (const float*)d_in[0];
    const int*   indices = (const int*)d_in[1];
    const float* upd     = (const float*)d_in[2];
    const int*   qs      = (const int*)d_in[3];
    float* out = (float*)d_out;

    // K1: N_UPD threads = 1024 blocks (exact). g_head all-zero on entry.
    link_kernel<<<1024, 256>>>(indices);
    // K2: N_Q*4 threads = 12800 blocks (exact)
    gather_kernel<<<12800, 256>>>(table, qs, upd, out);
    // K3: restore g_head == 0 via a graph memset node (contiguous 4 MB,
    // no index-load dependency; faster than a scatter-clear kernel).
    void* head_ptr = nullptr;
    cudaGetSymbolAddress(&head_ptr, g_head);
    cudaMemsetAsync(head_ptr, 0, sizeof(int) * (1 << 20));
}

// round 14
// speedup vs baseline: 1.0246x; 1.0246x over previous
#include <cuda_runtime.h>
#include <cstdint>

// Problem constants (match reference_code)
#define VOC_SIZE 1000000
#define EMBED_DIM 64
#define N_UPD 262144
#define N_Q (4096 * 200)  // 819200 query rows

// Scratch (allocation-free __device__ globals).
// Per-row linked list of updates:
//   g_head[row] = 1 + index of the last update hitting `row` (0 = untouched)
//   g_next[i]   = 1 + index of the previous update hitting the same row
// Invariant: g_head is all-zero at entry to every kernel_launch invocation
// (zero-initialized at module load; a graph memset node restores it at the
// end of each invocation).
__device__ int g_head[1 << 20];   // 4 MB (padded to power of two)
__device__ int g_next[N_UPD];     // 1 MB

typedef unsigned long long u64;

// 32-byte table load with L2 evict_last (sm_103a: modifier requires
// .v8.b32 / .v4.b64 width). Duplicate queries re-read table rows; bias them
// to stay resident in L2.
__device__ __forceinline__ void ldg_evict_last_32B(const float* p,
                                                   u64& x, u64& y, u64& z, u64& w) {
    asm("ld.global.nc.L2::evict_last.v4.b64 {%0,%1,%2,%3}, [%4];"
        : "=l"(x), "=l"(y), "=l"(z), "=l"(w) : "l"(p));
}

// Streaming store (evict-first): output is written once and never re-read.
__device__ __forceinline__ void stg_cs_32B(float* p, u64 x, u64 y, u64 z, u64 w) {
    asm volatile("st.global.cs.v4.b64 [%0], {%1,%2,%3,%4};"
                 :: "l"(p), "l"(x), "l"(y), "l"(z), "l"(w) : "memory");
}

__device__ __forceinline__ u64 pack2(float lo, float hi) {
    return ((u64)__float_as_uint(hi) << 32) | (u64)__float_as_uint(lo);
}
__device__ __forceinline__ float f_lo(u64 v) { return __uint_as_float((unsigned)v); }
__device__ __forceinline__ float f_hi(u64 v) { return __uint_as_float((unsigned)(v >> 32)); }

// K1: build per-row linked lists of updates. Requires g_head == 0 on entry.
// Latency-pinned at ~6.5us regardless of occupancy/ILP config (measured);
// keep the simple 1-update-per-thread form.
__global__ void link_kernel(const int* __restrict__ indices) {
    int i = blockIdx.x * blockDim.x + threadIdx.x;   // 0 .. N_UPD-1
    int r = indices[i];
    int o = atomicExch(&g_head[r], i + 1);
    g_next[i] = o;
}

// K2: gather. out[q] = table[q] + sum over the update chain of row q.
// 8 threads per 256B row, 32B per thread; each thread handles TWO query rows
// (i, i+N_Q/2) with SERIALIZED chain walks (fusing them was measured slower:
// regs 56 -> occ 40%). __launch_bounds__(256,6) caps regs at ~42 so 6 blocks
// (48 warps, 75% occ) keep the DRAM stream fed — at DRAM=70% the kernel
// wants warps, not per-thread ILP. Table reads: L2 evict_last. Output:
// streaming stores.
__global__ void __launch_bounds__(256, 6)
gather_kernel(const float* __restrict__ table,
              const int* __restrict__ qs,
              const float* __restrict__ upd,
              float* __restrict__ out) {
    int t = blockIdx.x * blockDim.x + threadIdx.x;   // 0 .. N_Q*4-1
    int i0 = t >> 3;
    int j  = t & 7;
    int i1 = i0 + (N_Q / 2);

    int r0 = qs[i0];
    int r1 = qs[i1];
    size_t o0 = (size_t)r0 * EMBED_DIM + j * 8;
    size_t o1 = (size_t)r1 * EMBED_DIM + j * 8;

    u64 x0, y0, z0, w0, x1, y1, z1, w1;
    ldg_evict_last_32B(&table[o0], x0, y0, z0, w0);
    ldg_evict_last_32B(&table[o1], x1, y1, z1, w1);
    int p0 = g_head[r0];
    int p1 = g_head[r1];

    if (p0) {
        float4 sa = make_float4(0.f, 0.f, 0.f, 0.f);
        float4 sb = make_float4(0.f, 0.f, 0.f, 0.f);
        do {
            int i = p0 - 1;
            const float4* up = reinterpret_cast<const float4*>(
                &upd[(size_t)i * EMBED_DIM + j * 8]);
            float4 da = __ldg(up);
            float4 db = __ldg(up + 1);
            sa.x += da.x; sa.y += da.y; sa.z += da.z; sa.w += da.w;
            sb.x += db.x; sb.y += db.y; sb.z += db.z; sb.w += db.w;
            p0 = g_next[i];
        } while (p0);
        x0 = pack2(f_lo(x0) + sa.x, f_hi(x0) + sa.y);
        y0 = pack2(f_lo(y0) + sa.z, f_hi(y0) + sa.w);
        z0 = pack2(f_lo(z0) + sb.x, f_hi(z0) + sb.y);
        w0 = pack2(f_lo(w0) + sb.z, f_hi(w0) + sb.w);
    }
    if (p1) {
        float4 sa = make_float4(0.f, 0.f, 0.f, 0.f);
        float4 sb = make_float4(0.f, 0.f, 0.f, 0.f);
        do {
            int i = p1 - 1;
            const float4* up = reinterpret_cast<const float4*>(
                &upd[(size_t)i * EMBED_DIM + j * 8]);
            float4 da = __ldg(up);
            float4 db = __ldg(up + 1);
            sa.x += da.x; sa.y += da.y; sa.z += da.z; sa.w += da.w;
            sb.x += db.x; sb.y += db.y; sb.z += db.z; sb.w += db.w;
            p1 = g_next[i];
        } while (p1);
        x1 = pack2(f_lo(x1) + sa.x, f_hi(x1) + sa.y);
        y1 = pack2(f_lo(y1) + sa.z, f_hi(y1) + sa.w);
        z1 = pack2(f_lo(z1) + sb.x, f_hi(z1) + sb.y);
        w1 = pack2(f_lo(w1) + sb.z, f_hi(w1) + sb.w);
    }

    stg_cs_32B(&out[(size_t)i0 * EMBED_DIM + j * 8], x0, y0, z0, w0);
    stg_cs_32B(&out[(size_t)i1 * EMBED_DIM + j * 8], x1, y1, z1, w1);
}

extern "C" void kernel_launch(void* const* d_in, const int* in_sizes, int n_in,
                              void* d_out, int out_size) {
    // metadata order: kernel (f32), indices (i32), emb_update (f32), qs (i32)
    const float* table   = (const float*)d_in[0];
    const int*   indices = (const int*)d_in[1];
    const float* upd     = (const float*)d_in[2];
    const int*   qs      = (const int*)d_in[3];
    float* out = (float*)d_out;

    // K1: N_UPD threads = 1024 blocks (exact). g_head all-zero on entry.
    link_kernel<<<1024, 256>>>(indices);
    // K2: N_Q*4 threads = 12800 blocks (exact)
    gather_kernel<<<12800, 256>>>(table, qs, upd, out);
    // K3: restore g_head == 0 via a graph memset node (contiguous 4 MB,
    // no index-load dependency).
    void* head_ptr = nullptr;
    cudaGetSymbolAddress(&head_ptr, g_head);
    cudaMemsetAsync(head_ptr, 0, sizeof(int) * (1 << 20));
}

// round 15
// speedup vs baseline: 1.0521x; 1.0268x over previous
#include <cuda_runtime.h>
#include <cstdint>

// Problem constants (match reference_code)
#define VOC_SIZE 1000000
#define EMBED_DIM 64
#define N_UPD 262144
#define N_Q (4096 * 200)  // 819200 query rows

// Scratch (allocation-free __device__ globals).
// Per-row linked list of updates:
//   g_head[row] = 1 + index of the last update hitting `row` (0 = untouched)
//   g_next[i]   = 1 + index of the previous update hitting the same row
// Invariant: g_head is all-zero at entry to every kernel_launch invocation
// (zero-initialized at module load; a graph memset node restores it at the
// end of each invocation).
__device__ int g_head[1 << 20];   // 4 MB (padded to power of two)
__device__ int g_next[N_UPD];     // 1 MB

typedef unsigned long long u64;

// 32-byte table load with L2 evict_last (sm_103a: modifier requires
// .v8.b32 / .v4.b64 width). Duplicate queries re-read table rows; bias them
// to stay resident in L2.
__device__ __forceinline__ void ldg_evict_last_32B(const float* p,
                                                   u64& x, u64& y, u64& z, u64& w) {
    asm("ld.global.nc.L2::evict_last.v4.b64 {%0,%1,%2,%3}, [%4];"
        : "=l"(x), "=l"(y), "=l"(z), "=l"(w) : "l"(p));
}

// Plain 32-byte load (chain walk).
__device__ __forceinline__ void ldg_32B(const float* p,
                                        u64& x, u64& y, u64& z, u64& w) {
    asm("ld.global.nc.v4.b64 {%0,%1,%2,%3}, [%4];"
        : "=l"(x), "=l"(y), "=l"(z), "=l"(w) : "l"(p));
}

// Streaming store (evict-first): output is written once and never re-read.
__device__ __forceinline__ void stg_cs_32B(float* p, u64 x, u64 y, u64 z, u64 w) {
    asm volatile("st.global.cs.v4.b64 [%0], {%1,%2,%3,%4};"
                 :: "l"(p), "l"(x), "l"(y), "l"(z), "l"(w) : "memory");
}

__device__ __forceinline__ u64 pack2(float lo, float hi) {
    return ((u64)__float_as_uint(hi) << 32) | (u64)__float_as_uint(lo);
}
__device__ __forceinline__ float f_lo(u64 v) { return __uint_as_float((unsigned)v); }
__device__ __forceinline__ float f_hi(u64 v) { return __uint_as_float((unsigned)(v >> 32)); }

// Add packed quad b into packed quad a (componentwise fp32).
__device__ __forceinline__ void add_quad(u64& ax, u64& ay, u64& az, u64& aw,
                                         u64 bx, u64 by, u64 bz, u64 bw) {
    ax = pack2(f_lo(ax) + f_lo(bx), f_hi(ax) + f_hi(bx));
    ay = pack2(f_lo(ay) + f_lo(by), f_hi(ay) + f_hi(by));
    az = pack2(f_lo(az) + f_lo(bz), f_hi(az) + f_hi(bz));
    aw = pack2(f_lo(aw) + f_lo(bw), f_hi(aw) + f_hi(bw));
}

// K1: build per-row linked lists of updates. Requires g_head == 0 on entry.
// Latency-pinned at ~6.5us regardless of occupancy/ILP config (measured);
// keep the simple 1-update-per-thread form.
__global__ void link_kernel(const int* __restrict__ indices) {
    int i = blockIdx.x * blockDim.x + threadIdx.x;   // 0 .. N_UPD-1
    int r = indices[i];
    int o = atomicExch(&g_head[r], i + 1);
    g_next[i] = o;
}

// K2: gather. out[q] = table[q] + sum over the update chain of row q.
// 8 threads per 256B row, 32B per thread; each thread handles TWO query rows
// (i, i+N_Q/2) with serialized chain walks. __launch_bounds__(256,8): 64
// warps/SM — at DRAM=72% this kernel wants resident warps; possible spills
// land only on the rare chain-walk path. Table reads: L2 evict_last.
// Output: streaming stores.
__global__ void __launch_bounds__(256, 8)
gather_kernel(const float* __restrict__ table,
              const int* __restrict__ qs,
              const float* __restrict__ upd,
              float* __restrict__ out) {
    int t = blockIdx.x * blockDim.x + threadIdx.x;   // 0 .. N_Q*4-1
    int i0 = t >> 3;
    int j  = t & 7;
    int i1 = i0 + (N_Q / 2);

    int r0 = qs[i0];
    int r1 = qs[i1];
    size_t o0 = (size_t)r0 * EMBED_DIM + j * 8;
    size_t o1 = (size_t)r1 * EMBED_DIM + j * 8;

    u64 x0, y0, z0, w0, x1, y1, z1, w1;
    ldg_evict_last_32B(&table[o0], x0, y0, z0, w0);
    ldg_evict_last_32B(&table[o1], x1, y1, z1, w1);
    int p0 = g_head[r0];
    int p1 = g_head[r1];

    if (p0) {
        do {
            int i = p0 - 1;
            u64 dx, dy, dz, dw;
            ldg_32B(&upd[(size_t)i * EMBED_DIM + j * 8], dx, dy, dz, dw);
            add_quad(x0, y0, z0, w0, dx, dy, dz, dw);
            p0 = g_next[i];
        } while (p0);
    }
    if (p1) {
        do {
            int i = p1 - 1;
            u64 dx, dy, dz, dw;
            ldg_32B(&upd[(size_t)i * EMBED_DIM + j * 8], dx, dy, dz, dw);
            add_quad(x1, y1, z1, w1, dx, dy, dz, dw);
            p1 = g_next[i];
        } while (p1);
    }

    stg_cs_32B(&out[(size_t)i0 * EMBED_DIM + j * 8], x0, y0, z0, w0);
    stg_cs_32B(&out[(size_t)i1 * EMBED_DIM + j * 8], x1, y1, z1, w1);
}

extern "C" void kernel_launch(void* const* d_in, const int* in_sizes, int n_in,
                              void* d_out, int out_size) {
    // metadata order: kernel (f32), indices (i32), emb_update (f32), qs (i32)
    const float* table   = (const float*)d_in[0];
    const int*   indices = (const int*)d_in[1];
    const float* upd     = (const float*)d_in[2];
    const int*   qs      = (const int*)d_in[3];
    float* out = (float*)d_out;

    // K1: N_UPD threads = 1024 blocks (exact). g_head all-zero on entry.
    link_kernel<<<1024, 256>>>(indices);
    // K2: N_Q*4 threads = 12800 blocks (exact)
    gather_kernel<<<12800, 256>>>(table, qs, upd, out);
    // K3: restore g_head == 0 via a graph memset node (contiguous 4 MB,
    // no index-load dependency).
    void* head_ptr = nullptr;
    cudaGetSymbolAddress(&head_ptr, g_head);
    cudaMemsetAsync(head_ptr, 0, sizeof(int) * (1 << 20));
}

// round 16
// speedup vs baseline: 1.0727x; 1.0196x over previous
#include <cuda_runtime.h>
#include <cstdint>

// Problem constants (match reference_code)
#define VOC_SIZE 1000000
#define EMBED_DIM 64
#define N_UPD 262144
#define N_Q (4096 * 200)  // 819200 query rows

// Scratch (allocation-free __device__ globals).
// Per-row linked list of updates:
//   g_head[row] = 1 + index of the last update hitting `row` (0 = untouched)
//   g_next[i]   = 1 + index of the previous update hitting the same row
// Invariant: g_head is all-zero at entry to every kernel_launch invocation
// (zero-initialized at module load; a graph memset node restores it at the
// end of each invocation).
__device__ int g_head[1 << 20];   // 4 MB (padded to power of two)
__device__ int g_next[N_UPD];     // 1 MB

typedef unsigned long long u64;

// 32-byte table load with L2 evict_last (sm_103a: modifier requires
// .v8.b32 / .v4.b64 width). Duplicate queries re-read table rows; bias them
// to stay resident in L2.
__device__ __forceinline__ void ldg_evict_last_32B(const float* p,
                                                   u64& x, u64& y, u64& z, u64& w) {
    asm("ld.global.nc.L2::evict_last.v4.b64 {%0,%1,%2,%3}, [%4];"
        : "=l"(x), "=l"(y), "=l"(z), "=l"(w) : "l"(p));
}

// Plain 32-byte load (chain walk).
__device__ __forceinline__ void ldg_32B(const float* p,
                                        u64& x, u64& y, u64& z, u64& w) {
    asm("ld.global.nc.v4.b64 {%0,%1,%2,%3}, [%4];"
        : "=l"(x), "=l"(y), "=l"(z), "=l"(w) : "l"(p));
}

// Streaming store (evict-first): output is written once and never re-read.
__device__ __forceinline__ void stg_cs_32B(float* p, u64 x, u64 y, u64 z, u64 w) {
    asm volatile("st.global.cs.v4.b64 [%0], {%1,%2,%3,%4};"
                 :: "l"(p), "l"(x), "l"(y), "l"(z), "l"(w) : "memory");
}

__device__ __forceinline__ u64 pack2(float lo, float hi) {
    return ((u64)__float_as_uint(hi) << 32) | (u64)__float_as_uint(lo);
}
__device__ __forceinline__ float f_lo(u64 v) { return __uint_as_float((unsigned)v); }
__device__ __forceinline__ float f_hi(u64 v) { return __uint_as_float((unsigned)(v >> 32)); }

// Add packed quad b into packed quad a (componentwise fp32).
__device__ __forceinline__ void add_quad(u64& ax, u64& ay, u64& az, u64& aw,
                                         u64 bx, u64 by, u64 bz, u64 bw) {
    ax = pack2(f_lo(ax) + f_lo(bx), f_hi(ax) + f_hi(bx));
    ay = pack2(f_lo(ay) + f_lo(by), f_hi(ay) + f_hi(by));
    az = pack2(f_lo(az) + f_lo(bz), f_hi(az) + f_hi(bz));
    aw = pack2(f_lo(aw) + f_lo(bw), f_hi(aw) + f_hi(bw));
}

// K1: build per-row linked lists of updates. Requires g_head == 0 on entry.
// L2-atomic-throughput-pinned at ~6.5us (measured across occ/ILP configs);
// keep the simple 1-update-per-thread form.
__global__ void link_kernel(const int* __restrict__ indices) {
    int i = blockIdx.x * blockDim.x + threadIdx.x;   // 0 .. N_UPD-1
    int r = indices[i];
    int o = atomicExch(&g_head[r], i + 1);
    g_next[i] = o;
}

// K2: gather. out[q] = table[q] + sum over the update chain of row q.
// 8 threads per 256B row, 32B per thread; each thread handles TWO query rows
// (i, i+N_Q/2) with serialized chain walks (fused walks + 4-way both
// measured slower via reg pressure). 128-thread blocks @16/SM keep the same
// 64-warp ceiling but pack tail waves tighter. Row 0's store issues before
// row 1's walk to shorten the dependency tail. Table reads: L2 evict_last.
// Output: streaming stores.
__global__ void __launch_bounds__(128, 16)
gather_kernel(const float* __restrict__ table,
              const int* __restrict__ qs,
              const float* __restrict__ upd,
              float* __restrict__ out) {
    int t = blockIdx.x * blockDim.x + threadIdx.x;   // 0 .. N_Q*4-1
    int i0 = t >> 3;
    int j  = t & 7;
    int i1 = i0 + (N_Q / 2);

    int r0 = qs[i0];
    int r1 = qs[i1];
    size_t o0 = (size_t)r0 * EMBED_DIM + j * 8;
    size_t o1 = (size_t)r1 * EMBED_DIM + j * 8;

    u64 x0, y0, z0, w0, x1, y1, z1, w1;
    ldg_evict_last_32B(&table[o0], x0, y0, z0, w0);
    ldg_evict_last_32B(&table[o1], x1, y1, z1, w1);
    int p0 = g_head[r0];
    int p1 = g_head[r1];

    if (p0) {
        do {
            int i = p0 - 1;
            u64 dx, dy, dz, dw;
            ldg_32B(&upd[(size_t)i * EMBED_DIM + j * 8], dx, dy, dz, dw);
            add_quad(x0, y0, z0, w0, dx, dy, dz, dw);
            p0 = g_next[i];
        } while (p0);
    }
    // Store row 0 before walking row 1's chain: starts the store early and
    // releases its registers on the walk path.
    stg_cs_32B(&out[(size_t)i0 * EMBED_DIM + j * 8], x0, y0, z0, w0);

    if (p1) {
        do {
            int i = p1 - 1;
            u64 dx, dy, dz, dw;
            ldg_32B(&upd[(size_t)i * EMBED_DIM + j * 8], dx, dy, dz, dw);
            add_quad(x1, y1, z1, w1, dx, dy, dz, dw);
            p1 = g_next[i];
        } while (p1);
    }
    stg_cs_32B(&out[(size_t)i1 * EMBED_DIM + j * 8], x1, y1, z1, w1);
}

extern "C" void kernel_launch(void* const* d_in, const int* in_sizes, int n_in,
                              void* d_out, int out_size) {
    // metadata order: kernel (f32), indices (i32), emb_update (f32), qs (i32)
    const float* table   = (const float*)d_in[0];
    const int*   indices = (const int*)d_in[1];
    const float* upd     = (const float*)d_in[2];
    const int*   qs      = (const int*)d_in[3];
    float* out = (float*)d_out;

    // K1: N_UPD threads = 1024 blocks (exact). g_head all-zero on entry.
    link_kernel<<<1024, 256>>>(indices);
    // K2: N_Q*4 threads = 25600 blocks of 128 (exact)
    gather_kernel<<<25600, 128>>>(table, qs, upd, out);
    // K3: restore g_head == 0 via a graph memset node (contiguous 4 MB,
    // no index-load dependency).
    void* head_ptr = nullptr;
    cudaGetSymbolAddress(&head_ptr, g_head);
    cudaMemsetAsync(head_ptr, 0, sizeof(int) * (1 << 20));
}